// round 2
// baseline (speedup 1.0000x reference)
#include <cuda_runtime.h>

#define BS 8
#define CI 256
#define CO 256
#define HH 128
#define WW 128
#define EPSV 1e-6f

#define CO_TILE 32
#define ROWS 8
#define COLS 64
#define XROWS 10      // ROWS + 2 halo
#define XCOLS 66      // COLS + 2 halo
#define XPITCH 72     // padded pitch
#define XTOT (XROWS*XCOLS)   // 660

// scratch (no cudaMalloc allowed)
__device__ float g_wt[CI * CO * 5];     // weights transposed to [ci][co][s]
__device__ float g_demod[BS * CO];      // d[b,o]

// ---------------- prologue: transpose weights [o][ci][5] -> [ci][co][5] ----------------
__global__ void transpose_w_kernel(const float* __restrict__ w) {
    int ci = blockIdx.x;
    int o = threadIdx.x;
#pragma unroll
    for (int s = 0; s < 5; s++)
        g_wt[(ci * CO + o) * 5 + s] = w[(o * CI + ci) * 5 + s];
}

// ---------------- prologue: demod d[b,o] = rsqrt(sum_ci m^2 * sum_s w^2 + eps) ----------
__global__ void demod_kernel(const float* __restrict__ y, const float* __restrict__ w) {
    int o = blockIdx.x;
    int b = blockIdx.y;
    int ci = threadIdx.x;
    float m = 1.0f + y[b * CI + ci];
    const float* wr = w + (o * CI + ci) * 5;
    float s = wr[0]*wr[0] + wr[1]*wr[1] + wr[2]*wr[2] + wr[3]*wr[3] + wr[4]*wr[4];
    float v = m * m * s;
#pragma unroll
    for (int off = 16; off; off >>= 1) v += __shfl_xor_sync(0xffffffffu, v, off);
    __shared__ float red[8];
    if ((threadIdx.x & 31) == 0) red[threadIdx.x >> 5] = v;
    __syncthreads();
    if (threadIdx.x == 0) {
        float t = red[0]+red[1]+red[2]+red[3]+red[4]+red[5]+red[6]+red[7];
        g_demod[b * CO + o] = rsqrtf(t + EPSV);
    }
}

// ---------------- main conv: 5-tap stencil, weights batch-shared, m folded into x -------
__global__ __launch_bounds__(256, 2) void conv_main_kernel(
    const float* __restrict__ x, const float* __restrict__ y, float* __restrict__ out)
{
    __shared__ float xs[2][XROWS * XPITCH];
    __shared__ float ws[2][CO_TILE * 5];
    __shared__ float ms[CI];

    const int tid  = threadIdx.x;
    const int lane = tid & 31;
    const int wrp  = tid >> 5;
    const int colseg = wrp & 1;   // which 32-col segment
    const int cog    = wrp >> 1;  // which group of 8 output channels

    const int tileid = blockIdx.x;
    const int r0 = (tileid >> 1) * ROWS;
    const int c0 = (tileid & 1) * COLS;
    const int o0 = blockIdx.y * CO_TILE;
    const int b  = blockIdx.z;

    ms[tid] = 1.0f + y[b * CI + tid];
    __syncthreads();

    // precompute prefetch addressing (per-thread, ci-invariant)
    int soff[3], goff[3];
    bool ok[3], st[3];
#pragma unroll
    for (int i = 0; i < 3; i++) {
        int idx = tid + i * 256;
        int r = idx / XCOLS, c = idx % XCOLS;
        st[i]   = (idx < XTOT);
        soff[i] = r * XPITCH + c;
        int gr = r0 - 1 + r, gc = c0 - 1 + c;
        ok[i]   = st[i] && (gr >= 0) && (gr < HH) && (gc >= 0) && (gc < WW);
        goff[i] = ok[i] ? (gr * WW + gc) : 0;
    }

    const float* xg = x + (long long)b * CI * HH * WW;

    // load ci = 0 into buffer 0
    {
        float v[3];
#pragma unroll
        for (int i = 0; i < 3; i++) v[i] = ok[i] ? xg[goff[i]] : 0.0f;
        float m0 = ms[0];
#pragma unroll
        for (int i = 0; i < 3; i++) if (st[i]) xs[0][soff[i]] = v[i] * m0;
        if (tid < CO_TILE * 5) ws[0][tid] = g_wt[(0 * CO + o0) * 5 + tid];
    }
    __syncthreads();

    float acc[64];
#pragma unroll
    for (int i = 0; i < 64; i++) acc[i] = 0.0f;

    const int cc = colseg * 32 + lane;  // tile column 0..63

    int cur = 0;
    for (int ci = 0; ci < CI; ci++) {
        const bool more = (ci + 1 < CI);
        float v[3] = {0.f, 0.f, 0.f};
        float wv = 0.f;
        if (more) {
            const float* xp = xg + (long long)(ci + 1) * HH * WW;
#pragma unroll
            for (int i = 0; i < 3; i++) v[i] = ok[i] ? xp[goff[i]] : 0.0f;
            if (tid < CO_TILE * 5) wv = g_wt[((ci + 1) * CO + o0) * 5 + tid];
        }

        // compute from current buffer
        const float* xb = xs[cur];
        float xc[10], xl[8], xr[8];
#pragma unroll
        for (int k = 0; k < 10; k++) xc[k] = xb[k * XPITCH + cc + 1];
#pragma unroll
        for (int k = 0; k < 8; k++) {
            xl[k] = xb[(k + 1) * XPITCH + cc];
            xr[k] = xb[(k + 1) * XPITCH + cc + 2];
        }
        const float* wb = ws[cur];
#pragma unroll
        for (int j = 0; j < 8; j++) {
            const int cj = (cog * 8 + j) * 5;
            const float w0 = wb[cj + 0];
            const float w1 = wb[cj + 1];
            const float w2 = wb[cj + 2];
            const float w3 = wb[cj + 3];
            const float w4 = wb[cj + 4];
#pragma unroll
            for (int k = 0; k < 8; k++) {
                float a = acc[j * 8 + k];
                a = fmaf(w0, xc[k],     a);   // top    (h-1, w)
                a = fmaf(w1, xl[k],     a);   // left   (h, w-1)
                a = fmaf(w2, xc[k + 1], a);   // center (h, w)
                a = fmaf(w3, xr[k],     a);   // right  (h, w+1)
                a = fmaf(w4, xc[k + 2], a);   // bottom (h+1, w)
                acc[j * 8 + k] = a;
            }
        }

        if (more) {
            float mm = ms[ci + 1];
#pragma unroll
            for (int i = 0; i < 3; i++) if (st[i]) xs[cur ^ 1][soff[i]] = v[i] * mm;
            if (tid < CO_TILE * 5) ws[cur ^ 1][tid] = wv;
        }
        __syncthreads();
        cur ^= 1;
    }

    // epilogue: scale by d[b,o] and store (lane = column -> coalesced)
#pragma unroll
    for (int j = 0; j < 8; j++) {
        const int o = o0 + cog * 8 + j;
        const float ds = g_demod[b * CO + o];
        float* op = out + ((long long)(b * CO + o) * HH + r0) * WW + c0 + cc;
#pragma unroll
        for (int k = 0; k < 8; k++)
            op[k * WW] = acc[j * 8 + k] * ds;
    }
}

extern "C" void kernel_launch(void* const* d_in, const int* in_sizes, int n_in,
                              void* d_out, int out_size) {
    const float* x = (const float*)d_in[0];
    const float* y = (const float*)d_in[1];
    const float* w = (const float*)d_in[2];
    // d_in[3] = stencil_index (fixed plus-stencil [1,3,4,5,7]; hardcoded in tap mapping)
    float* out = (float*)d_out;

    transpose_w_kernel<<<CI, CO>>>(w);
    demod_kernel<<<dim3(CO, BS), CI>>>(y, w);

    dim3 grid((HH / ROWS) * (WW / COLS), CO / CO_TILE, BS);
    conv_main_kernel<<<grid, 256>>>(x, y, out);
}

// round 4
// speedup vs baseline: 3.7443x; 3.7443x over previous
#include <cuda_runtime.h>
#include <cstdint>
#include <cstddef>

#define BS 8
#define CI 256
#define CO 256
#define HH 128
#define WW 128
#define EPSV 1e-6f

#define CKN 16                    // ci chunks
#define CIC 16                    // ci per chunk
#define XCIP 392                  // floats per ci in X smem: 3*128 + 8 pad (bank skew)
#define WPITCH 136                // co pitch in W smem (bank skew)
#define XF (CIC * XCIP)           // 6272 floats  (25088 B)
#define WF (5 * CIC * WPITCH)     // 10880 floats (43520 B)
#define STAGEF (XF + WF)          // 17152 floats (68608 B)
#define SMEM_DYN (2 * STAGEF * 4) // 137216 B
#define TXBYTES (CIC * 1536 + WF * 4)   // 24576 + 43520 = 68096

// ---------------- device scratch (no cudaMalloc allowed) ----------------
// modulated tf32 weights, laid out exactly as the SMEM W tile per (b, cotile, ck):
// [tap][ci16][co 128 + 8 pad]
__device__ float g_weff[(size_t)BS * 2 * CKN * WF];
__device__ float g_demod[BS * CO];
__device__ __align__(512) float g_zero[384];   // zero halo rows (zero-initialized .bss)

// ---------------- PTX helpers (all base-sm_103 legal; NO tcgen05) ----------------
__device__ __forceinline__ uint32_t smem_u32(const void* p) {
    uint32_t a;
    asm("{ .reg .u64 t; cvta.to.shared.u64 t, %1; cvt.u32.u64 %0, t; }" : "=r"(a) : "l"(p));
    return a;
}
__device__ __forceinline__ float to_tf32(float v) {
    float r;
    asm("cvt.rna.tf32.f32 %0, %1;" : "=f"(r) : "f"(v));
    return r;
}
__device__ __forceinline__ uint32_t f2tf(float v) {
    uint32_t r;
    asm("cvt.rna.tf32.f32 %0, %1;" : "=r"(r) : "f"(v));
    return r;
}
__device__ __forceinline__ void mbar_init(uint32_t mbar, uint32_t cnt) {
    asm volatile("mbarrier.init.shared.b64 [%0], %1;" :: "r"(mbar), "r"(cnt) : "memory");
}
__device__ __forceinline__ void mbar_expect_tx(uint32_t mbar, uint32_t bytes) {
    asm volatile("mbarrier.arrive.expect_tx.shared.b64 _, [%0], %1;"
                 :: "r"(mbar), "r"(bytes) : "memory");
}
__device__ __forceinline__ void mbar_wait(uint32_t mbar, uint32_t parity) {
    asm volatile(
        "{\n\t.reg .pred P;\n\t"
        "WL_%=:\n\t"
        "mbarrier.try_wait.parity.acquire.cta.shared::cta.b64 P, [%0], %1, 0x989680;\n\t"
        "@P bra.uni WD_%=;\n\t"
        "bra.uni WL_%=;\n\t"
        "WD_%=:\n\t}"
        :: "r"(mbar), "r"(parity) : "memory");
}
__device__ __forceinline__ void bulk_g2s(uint32_t dst, const void* src, uint32_t bytes, uint32_t mbar) {
    asm volatile(
        "cp.async.bulk.shared::cluster.global.mbarrier::complete_tx::bytes [%0], [%1], %2, [%3];"
        :: "r"(dst), "l"(src), "r"(bytes), "r"(mbar) : "memory");
}
__device__ __forceinline__ void fence_async() {
    asm volatile("fence.proxy.async.shared::cta;" ::: "memory");
}
// m16n8k8 tf32 MMA: D += A*B, A row-major 16x8, B col-major 8x8, fp32 accum
__device__ __forceinline__ void mma8(float* d, const uint32_t* a, uint32_t b0, uint32_t b1) {
    asm volatile(
        "mma.sync.aligned.m16n8k8.row.col.f32.tf32.tf32.f32 "
        "{%0,%1,%2,%3}, {%4,%5,%6,%7}, {%8,%9}, {%0,%1,%2,%3};"
        : "+f"(d[0]), "+f"(d[1]), "+f"(d[2]), "+f"(d[3])
        : "r"(a[0]), "r"(a[1]), "r"(a[2]), "r"(a[3]), "r"(b0), "r"(b1));
}

// ---------------- prologue: modulated tf32 weights in SMEM-tile layout ----------------
__global__ __launch_bounds__(128) void prep_w_kernel(
    const float* __restrict__ w, const float* __restrict__ y)
{
    const int ck = blockIdx.x, ct = blockIdx.y, b = blockIdx.z;
    const int co = threadIdx.x;                 // 0..127
    const int o = ct * 128 + co;
    float* blk = g_weff + ((size_t)((b * 2 + ct) * CKN + ck)) * WF;
#pragma unroll
    for (int cl = 0; cl < CIC; cl++) {
        const int ci = ck * CIC + cl;
        const float m = 1.0f + y[b * CI + ci];
        const float* wp = w + ((size_t)o * CI + ci) * 5;
#pragma unroll
        for (int tap = 0; tap < 5; tap++)
            blk[(tap * CIC + cl) * WPITCH + co] = to_tf32(wp[tap] * m);
    }
}

// ---------------- prologue: demod ----------------
__global__ void demod_kernel(const float* __restrict__ y, const float* __restrict__ w) {
    int o = blockIdx.x, b = blockIdx.y, ci = threadIdx.x;
    float m = 1.0f + y[b * CI + ci];
    const float* wr = w + ((size_t)o * CI + ci) * 5;
    float s = wr[0]*wr[0] + wr[1]*wr[1] + wr[2]*wr[2] + wr[3]*wr[3] + wr[4]*wr[4];
    float v = m * m * s;
#pragma unroll
    for (int off = 16; off; off >>= 1) v += __shfl_xor_sync(0xffffffffu, v, off);
    __shared__ float red[8];
    if ((threadIdx.x & 31) == 0) red[threadIdx.x >> 5] = v;
    __syncthreads();
    if (threadIdx.x == 0) {
        float t = red[0]+red[1]+red[2]+red[3]+red[4]+red[5]+red[6]+red[7];
        g_demod[b * CO + o] = rsqrtf(t + EPSV);
    }
}

// ---------------- producer: bulk-copy one chunk into a stage ----------------
__device__ __forceinline__ void issue_chunk(
    int c, int s, int h, int b, int ct, const float* __restrict__ x,
    uint32_t smem_base, uint32_t mb)
{
    const uint32_t xdst = smem_base + (uint32_t)s * (STAGEF * 4);
    mbar_expect_tx(mb, TXBYTES);
    if (h > 0 && h < HH - 1) {
        // interior: rows h-1..h+1 contiguous in global per ci -> one 1536B copy
        for (int ci = 0; ci < CIC; ci++) {
            const int cig = c * CIC + ci;
            const float* src = x + (((size_t)(b * CI + cig) * HH + (h - 1)) * WW);
            bulk_g2s(xdst + ci * (XCIP * 4), src, 1536, mb);
        }
    } else {
        for (int ci = 0; ci < CIC; ci++) {
            const int cig = c * CIC + ci;
            for (int r = 0; r < 3; r++) {
                const int hr = h + r - 1;
                const float* src = (hr >= 0 && hr < HH)
                    ? x + (((size_t)(b * CI + cig) * HH + hr) * WW)
                    : g_zero;
                bulk_g2s(xdst + ci * (XCIP * 4) + r * 512, src, 512, mb);
            }
        }
    }
    bulk_g2s(xdst + XF * 4,
             g_weff + ((size_t)((b * 2 + ct) * CKN + c)) * WF, WF * 4, mb);
}

// ---------------- main: tf32 mma.sync implicit-GEMM stencil ----------------
__global__ __launch_bounds__(256, 1) void conv_mma_kernel(
    const float* __restrict__ x, float* __restrict__ out)
{
    extern __shared__ float smem[];
    __shared__ uint64_t s_mbar[2];
    __shared__ float sd[128];

    const int tid  = threadIdx.x;
    const int lane = tid & 31;
    const int wid  = tid >> 5;
    const int grp  = lane >> 2;   // 0..7
    const int tig  = lane & 3;    // 0..3
    const int mg = wid >> 1;      // 4 M-groups of 32 pixels
    const int ng = wid & 1;       // 2 N-groups of 64 co
    const int mbase = mg * 32;

    const int h  = blockIdx.x;
    const int ct = blockIdx.y;
    const int b  = blockIdx.z;

    const uint32_t smem_base = smem_u32(smem);
    const uint32_t mb0 = smem_u32(&s_mbar[0]);
    const uint32_t mb1 = smem_u32(&s_mbar[1]);

    if (tid < 128) sd[tid] = g_demod[b * CO + ct * 128 + tid];
    if (tid == 0) {
        mbar_init(mb0, 1);
        mbar_init(mb1, 1);
        fence_async();
    }
    __syncthreads();
    if (tid == 0) {
        issue_chunk(0, 0, h, b, ct, x, smem_base, mb0);
        issue_chunk(1, 1, h, b, ct, x, smem_base, mb1);
    }

    float d[2][8][4];
#pragma unroll
    for (int f = 0; f < 2; f++)
#pragma unroll
        for (int nf = 0; nf < 8; nf++)
#pragma unroll
            for (int k = 0; k < 4; k++) d[f][nf][k] = 0.0f;

    for (int c = 0; c < CKN; c++) {
        const int s = c & 1;
        mbar_wait(s ? mb1 : mb0, (c >> 1) & 1);
        const float* xs = smem + s * STAGEF;
        const float* ws = xs + XF;

#pragma unroll
        for (int tap = 0; tap < 5; tap++) {
            const int row   = (tap == 0) ? 0 : (tap == 4 ? 2 : 1);
            const int shift = (tap == 1) ? -1 : (tap == 3 ? 1 : 0);
#pragma unroll
            for (int ks = 0; ks < 2; ks++) {
                const int kb = ks * 8;
                uint32_t a[2][4];
#pragma unroll
                for (int f = 0; f < 2; f++) {
                    const int p   = mbase + f * 16 + grp;
                    const int sp  = p + shift;
                    const int sp2 = sp + 8;
                    const bool v1 = (unsigned)sp  < (unsigned)WW;
                    const bool v2 = (unsigned)sp2 < (unsigned)WW;
                    const float* b0 = xs + (kb + tig) * XCIP + row * WW;
                    const float* b1 = xs + (kb + tig + 4) * XCIP + row * WW;
                    a[f][0] = f2tf(v1 ? b0[sp]  : 0.0f);
                    a[f][1] = f2tf(v2 ? b0[sp2] : 0.0f);
                    a[f][2] = f2tf(v1 ? b1[sp]  : 0.0f);
                    a[f][3] = f2tf(v2 ? b1[sp2] : 0.0f);
                }
#pragma unroll
                for (int nf = 0; nf < 8; nf++) {
                    const int co = ng * 64 + nf * 8 + grp;
                    const float* wb = ws + (tap * CIC + kb + tig) * WPITCH + co;
                    const uint32_t bb0 = __float_as_uint(wb[0]);
                    const uint32_t bb1 = __float_as_uint(wb[4 * WPITCH]);
                    mma8(d[0][nf], a[0], bb0, bb1);
                    mma8(d[1][nf], a[1], bb0, bb1);
                }
            }
        }
        __syncthreads();   // all reads of stage s done -> safe to reload
        if (tid == 0 && c + 2 < CKN)
            issue_chunk(c + 2, s, h, b, ct, x, smem_base, s ? mb1 : mb0);
    }

    // ---- epilogue: demod scale + store ----
    float* ob = out + (((size_t)b * CO + ct * 128) * HH + h) * WW;
#pragma unroll
    for (int f = 0; f < 2; f++) {
        const int p = mbase + f * 16 + grp;
#pragma unroll
        for (int nf = 0; nf < 8; nf++) {
            const int co0 = ng * 64 + nf * 8 + tig * 2;
            const float s0 = sd[co0], s1 = sd[co0 + 1];
            ob[(size_t)co0 * (HH * WW) + p]           = d[f][nf][0] * s0;
            ob[(size_t)(co0 + 1) * (HH * WW) + p]     = d[f][nf][1] * s1;
            ob[(size_t)co0 * (HH * WW) + p + 8]       = d[f][nf][2] * s0;
            ob[(size_t)(co0 + 1) * (HH * WW) + p + 8] = d[f][nf][3] * s1;
        }
    }
}

extern "C" void kernel_launch(void* const* d_in, const int* in_sizes, int n_in,
                              void* d_out, int out_size) {
    const float* x = (const float*)d_in[0];
    const float* y = (const float*)d_in[1];
    const float* w = (const float*)d_in[2];
    float* out = (float*)d_out;

    cudaFuncSetAttribute(conv_mma_kernel, cudaFuncAttributeMaxDynamicSharedMemorySize, SMEM_DYN);

    prep_w_kernel<<<dim3(CKN, 2, BS), 128>>>(w, y);
    demod_kernel<<<dim3(CO, BS), 256>>>(y, w);
    conv_mma_kernel<<<dim3(HH, 2, BS), 256, SMEM_DYN>>>(x, out);
}

// round 5
// speedup vs baseline: 3.9751x; 1.0617x over previous
#include <cuda_runtime.h>
#include <cstdint>
#include <cstddef>

#define BS 8
#define CI 256
#define CO 256
#define HH 128
#define WW 128
#define EPSV 1e-6f

#define CKN 16                    // ci chunks of 16
// Stage layout (floats):
//  X: [xrow 4][ks 2][pix 128][8]  = 8192 floats (32 KB)
//  W: [tap 5][ks 2][co 128][8]    = 10240 floats (40 KB)
#define XF 8192
#define WF 10240
#define STAGEF (XF + WF)          // 18432 floats = 73728 B
#define NSTAGE 3
#define TXBYTES (STAGEF * 4)
#define SMEM_DYN (NSTAGE * STAGEF * 4 + 256)

// ---------------- device scratch (no cudaMalloc allowed) ----------------
// x: tf32-rounded, transposed+pair-interleaved: block (b*16+ck)*128+h of 2048 floats:
//    [ks][pix][tig*2+pair], where local ci j = ks*8 + pair*4 + tig
__device__ __align__(16) float g_xt[(size_t)BS * CKN * HH * 2048];
// w_eff = tf32(w * (1+y) * demod): block ((b*2+ct)*16+ck) of WF floats:
//    [tap][ks][co][tig*2+pair]
__device__ __align__(16) float g_weff[(size_t)BS * 2 * CKN * WF];
__device__ float g_demod[BS * CO];
__device__ __align__(16) float g_zero[2048];   // zero halo row (.bss)

// ---------------- PTX helpers (base sm_103 legal; NO tcgen05) ----------------
__device__ __forceinline__ uint32_t smem_u32(const void* p) {
    uint32_t a;
    asm("{ .reg .u64 t; cvta.to.shared.u64 t, %1; cvt.u32.u64 %0, t; }" : "=r"(a) : "l"(p));
    return a;
}
__device__ __forceinline__ float to_tf32(float v) {
    float r;
    asm("cvt.rna.tf32.f32 %0, %1;" : "=f"(r) : "f"(v));
    return r;
}
__device__ __forceinline__ void mbar_init(uint32_t mbar, uint32_t cnt) {
    asm volatile("mbarrier.init.shared.b64 [%0], %1;" :: "r"(mbar), "r"(cnt) : "memory");
}
__device__ __forceinline__ void mbar_expect_tx(uint32_t mbar, uint32_t bytes) {
    asm volatile("mbarrier.arrive.expect_tx.shared.b64 _, [%0], %1;"
                 :: "r"(mbar), "r"(bytes) : "memory");
}
__device__ __forceinline__ void mbar_arrive(uint32_t mbar) {
    asm volatile("mbarrier.arrive.shared.b64 _, [%0];" :: "r"(mbar) : "memory");
}
__device__ __forceinline__ void mbar_wait(uint32_t mbar, uint32_t parity) {
    asm volatile(
        "{\n\t.reg .pred P;\n\t"
        "WL_%=:\n\t"
        "mbarrier.try_wait.parity.acquire.cta.shared::cta.b64 P, [%0], %1, 0x989680;\n\t"
        "@P bra.uni WD_%=;\n\t"
        "bra.uni WL_%=;\n\t"
        "WD_%=:\n\t}"
        :: "r"(mbar), "r"(parity) : "memory");
}
__device__ __forceinline__ void bulk_g2s(uint32_t dst, const void* src, uint32_t bytes, uint32_t mbar) {
    asm volatile(
        "cp.async.bulk.shared::cluster.global.mbarrier::complete_tx::bytes [%0], [%1], %2, [%3];"
        :: "r"(dst), "l"(src), "r"(bytes), "r"(mbar) : "memory");
}
__device__ __forceinline__ void fence_async() {
    asm volatile("fence.proxy.async.shared::cta;" ::: "memory");
}
__device__ __forceinline__ void mma8(float* d, const uint32_t* a, uint32_t b0, uint32_t b1) {
    asm volatile(
        "mma.sync.aligned.m16n8k8.row.col.f32.tf32.tf32.f32 "
        "{%0,%1,%2,%3}, {%4,%5,%6,%7}, {%8,%9}, {%0,%1,%2,%3};"
        : "+f"(d[0]), "+f"(d[1]), "+f"(d[2]), "+f"(d[3])
        : "r"(a[0]), "r"(a[1]), "r"(a[2]), "r"(a[3]), "r"(b0), "r"(b1));
}

// ---------------- prologue: demod ----------------
__global__ void demod_kernel(const float* __restrict__ y, const float* __restrict__ w) {
    int o = blockIdx.x, b = blockIdx.y, ci = threadIdx.x;
    float m = 1.0f + y[b * CI + ci];
    const float* wr = w + ((size_t)o * CI + ci) * 5;
    float s = wr[0]*wr[0] + wr[1]*wr[1] + wr[2]*wr[2] + wr[3]*wr[3] + wr[4]*wr[4];
    float v = m * m * s;
#pragma unroll
    for (int off = 16; off; off >>= 1) v += __shfl_xor_sync(0xffffffffu, v, off);
    __shared__ float red[8];
    if ((threadIdx.x & 31) == 0) red[threadIdx.x >> 5] = v;
    __syncthreads();
    if (threadIdx.x == 0) {
        float t = red[0]+red[1]+red[2]+red[3]+red[4]+red[5]+red[6]+red[7];
        g_demod[b * CO + o] = rsqrtf(t + EPSV);
    }
}

// ---------------- prologue: x transpose + tf32 round + pair interleave ----------------
__global__ __launch_bounds__(256) void prep_x_kernel(const float* __restrict__ x) {
    __shared__ float xs[16][132];
    const int t = threadIdx.x;
    const int h = blockIdx.x, ck = blockIdx.y, b = blockIdx.z;

    const float* src = x + ((size_t)(b * CI + ck * 16) * HH + h) * WW;
#pragma unroll
    for (int r = 0; r < 8; r++) {
        int idx = t + r * 256;
        int j = idx >> 7, pix = idx & 127;
        xs[j][pix] = src[(size_t)j * HH * WW + pix];
    }
    __syncthreads();

    float* dst = g_xt + ((size_t)((b * CKN + ck) * HH + h)) * 2048;
#pragma unroll
    for (int r = 0; r < 8; r++) {
        int o = t + r * 256;
        int ks = o >> 10, pix = (o >> 3) & 127, l8 = o & 7;
        int tig = l8 >> 1, pair = l8 & 1;
        int j = ks * 8 + pair * 4 + tig;
        dst[o] = to_tf32(xs[j][pix]);
    }
}

// ---------------- prologue: modulated+demodulated tf32 weights (SMEM layout) ----------
__global__ __launch_bounds__(128) void prep_w_kernel(
    const float* __restrict__ w, const float* __restrict__ y)
{
    const int ck = blockIdx.x, ct = blockIdx.y, b = blockIdx.z;
    const int co = threadIdx.x;
    const int o = ct * 128 + co;
    const float dd = g_demod[b * CO + o];
    float* blk = g_weff + ((size_t)((b * 2 + ct) * CKN + ck)) * WF;
#pragma unroll
    for (int j = 0; j < 16; j++) {
        const int ci = ck * 16 + j;
        const float m = (1.0f + y[b * CI + ci]) * dd;
        const int ks = j >> 3, rem = j & 7, pair = rem >> 2, tig = rem & 3;
        const float* wp = w + ((size_t)o * CI + ci) * 5;
#pragma unroll
        for (int tap = 0; tap < 5; tap++)
            blk[(((tap * 2 + ks) * 128 + co) << 3) + tig * 2 + pair] = to_tf32(wp[tap] * m);
    }
}

// ---------------- producer: one chunk into a stage ----------------
__device__ __forceinline__ void issue_chunk(
    int c, int h0, int b, int ct, uint32_t stage_dst, uint32_t full_mb)
{
    mbar_expect_tx(full_mb, TXBYTES);
    const float* xb = g_xt + ((size_t)(b * CKN + c) * HH) * 2048;
    if (h0 >= 2 && h0 <= 124) {
        bulk_g2s(stage_dst, xb + (size_t)(h0 - 1) * 2048, 32768, full_mb);
    } else if (h0 == 0) {
        bulk_g2s(stage_dst, g_zero, 8192, full_mb);
        bulk_g2s(stage_dst + 8192, xb, 24576, full_mb);
    } else { // h0 == 126
        bulk_g2s(stage_dst, xb + (size_t)125 * 2048, 24576, full_mb);
        bulk_g2s(stage_dst + 24576, g_zero, 8192, full_mb);
    }
    bulk_g2s(stage_dst + XF * 4,
             g_weff + ((size_t)((b * 2 + ct) * CKN + c)) * WF, WF * 4, full_mb);
}

// ---------------- main: tf32 mma.sync, M=256 (2 rows) x N=128, 3-stage pipeline ------
__global__ __launch_bounds__(256, 1) void conv_mma_kernel(float* __restrict__ out) {
    extern __shared__ float smem[];
    const uint32_t smem_base = smem_u32(smem);
    const uint32_t barbase = smem_base + NSTAGE * STAGEF * 4;

    const int tid  = threadIdx.x;
    const int lane = tid & 31;
    const int wid  = tid >> 5;
    const int grp  = lane >> 2;
    const int tig  = lane & 3;
    const int mg = wid >> 1;             // 0..3 : M64 tile index over M=256
    const int ng = wid & 1;              // 0..1 : N64 tile
    const int row = mg >> 1;             // output row within CTA (0/1)
    const int pbase = (mg & 1) * 64;     // pixel base

    const int h0 = blockIdx.x * 2;
    const int ct = blockIdx.y;
    const int b  = blockIdx.z;

    if (tid == 0) {
        for (int s = 0; s < NSTAGE; s++) {
            mbar_init(barbase + s * 8, 1);            // full
            mbar_init(barbase + 24 + s * 8, 8);       // empty (one arrive per warp)
        }
        fence_async();
    }
    __syncthreads();
    if (tid == 0)
        for (int c = 0; c < NSTAGE; c++)
            issue_chunk(c, h0, b, ct, smem_base + c * STAGEF * 4, barbase + c * 8);

    float d[4][8][4];
#pragma unroll
    for (int f = 0; f < 4; f++)
#pragma unroll
        for (int nf = 0; nf < 8; nf++)
#pragma unroll
            for (int k = 0; k < 4; k++) d[f][nf][k] = 0.0f;

    for (int c = 0; c < CKN; c++) {
        const int s = c % NSTAGE;
        const int r = c / NSTAGE;
        mbar_wait(barbase + s * 8, r & 1);
        const float* xs = smem + s * STAGEF;
        const float* ws = xs + XF;

#pragma unroll
        for (int tap = 0; tap < 5; tap++) {
            const int xrow  = row + ((tap == 0) ? 0 : (tap == 4 ? 2 : 1));
            const int shift = (tap == 1) ? -1 : ((tap == 3) ? 1 : 0);
#pragma unroll
            for (int ks = 0; ks < 2; ks++) {
                const float* xbase = xs + ((xrow * 2 + ks) << 10) + tig * 2;
                uint32_t a[4][4];
#pragma unroll
                for (int f = 0; f < 4; f++) {
                    const int sp = pbase + f * 16 + grp + shift;
                    uint2 lo = make_uint2(0u, 0u), hi = make_uint2(0u, 0u);
                    if ((unsigned)sp < (unsigned)WW)
                        lo = *(const uint2*)(xbase + sp * 8);
                    if ((unsigned)(sp + 8) < (unsigned)WW)
                        hi = *(const uint2*)(xbase + (sp + 8) * 8);
                    a[f][0] = lo.x; a[f][2] = lo.y;
                    a[f][1] = hi.x; a[f][3] = hi.y;
                }
                const float* wb = ws + (((tap * 2 + ks) * 128 + ng * 64 + grp) << 3) + tig * 2;
#pragma unroll
                for (int nf = 0; nf < 8; nf++) {
                    const uint2 bv = *(const uint2*)(wb + nf * 64);
                    mma8(d[0][nf], a[0], bv.x, bv.y);
                    mma8(d[1][nf], a[1], bv.x, bv.y);
                    mma8(d[2][nf], a[2], bv.x, bv.y);
                    mma8(d[3][nf], a[3], bv.x, bv.y);
                }
            }
        }
        if (lane == 0) mbar_arrive(barbase + 24 + s * 8);
        if (tid == 0 && c + NSTAGE < CKN) {
            mbar_wait(barbase + 24 + s * 8, r & 1);
            issue_chunk(c + NSTAGE, h0, b, ct, smem_base + s * STAGEF * 4, barbase + s * 8);
        }
    }

    // ---- epilogue: demod already folded into weights -> pure store ----
    float* ob = out + (((size_t)b * CO + ct * 128) * HH + (h0 + row)) * WW;
#pragma unroll
    for (int f = 0; f < 4; f++) {
        const int p = pbase + f * 16 + grp;
#pragma unroll
        for (int nf = 0; nf < 8; nf++) {
            const int co = ng * 64 + nf * 8 + tig * 2;
            ob[(size_t)co * (HH * WW) + p]           = d[f][nf][0];
            ob[(size_t)(co + 1) * (HH * WW) + p]     = d[f][nf][1];
            ob[(size_t)co * (HH * WW) + p + 8]       = d[f][nf][2];
            ob[(size_t)(co + 1) * (HH * WW) + p + 8] = d[f][nf][3];
        }
    }
}

extern "C" void kernel_launch(void* const* d_in, const int* in_sizes, int n_in,
                              void* d_out, int out_size) {
    const float* x = (const float*)d_in[0];
    const float* y = (const float*)d_in[1];
    const float* w = (const float*)d_in[2];
    float* out = (float*)d_out;

    cudaFuncSetAttribute(conv_mma_kernel, cudaFuncAttributeMaxDynamicSharedMemorySize, SMEM_DYN);

    demod_kernel<<<dim3(CO, BS), 256>>>(y, w);
    prep_x_kernel<<<dim3(HH, CKN, BS), 256>>>(x);
    prep_w_kernel<<<dim3(CKN, 2, BS), 128>>>(w, y);
    conv_mma_kernel<<<dim3(HH / 2, 2, BS), 256, SMEM_DYN>>>(out);
}

// round 6
// speedup vs baseline: 4.1326x; 1.0396x over previous
#include <cuda_runtime.h>
#include <cstdint>
#include <cstddef>

#define BS 8
#define CI 256
#define CO 256
#define HH 128
#define WW 128
#define EPSV 1e-6f

#define CKN 16                    // ci chunks of 16
// Stage layout (floats):
//  X: [xrow 4][ks 2][pix 130 padded][8] = 8320 floats (33280 B)
//  W: [tap 5][ks 2][co 128][8]          = 10240 floats (40960 B)
#define XF 8320
#define XROWF 2080                // one (h) block: [ks 2][130][8]
#define WF 10240
#define STAGEF (XF + WF)          // 18560 floats = 74240 B
#define NSTAGE 3
#define TXBYTES (STAGEF * 4)
#define SMEM_DYN (NSTAGE * STAGEF * 4 + 256)

// ---------------- device scratch (no cudaMalloc allowed) ----------------
// x: tf32-rounded, padded, pair-interleaved: block (b*16+ck)*128+h of 2080 floats:
//    [ks][pix 0..129][tig*2+pair], pix 0 and 129 are zero borders
__device__ __align__(16) float g_xt[(size_t)BS * CKN * HH * XROWF];
// w_eff = tf32(w * (1+y) * demod): block ((b*2+ct)*16+ck) of WF floats
__device__ __align__(16) float g_weff[(size_t)BS * 2 * CKN * WF];
__device__ float g_demod[BS * CO];
__device__ __align__(16) float g_zero[XROWF];   // zero halo row (.bss)

// ---------------- PTX helpers (base sm_103 legal; NO tcgen05) ----------------
__device__ __forceinline__ uint32_t smem_u32(const void* p) {
    uint32_t a;
    asm("{ .reg .u64 t; cvta.to.shared.u64 t, %1; cvt.u32.u64 %0, t; }" : "=r"(a) : "l"(p));
    return a;
}
__device__ __forceinline__ float to_tf32(float v) {
    float r;
    asm("cvt.rna.tf32.f32 %0, %1;" : "=f"(r) : "f"(v));
    return r;
}
__device__ __forceinline__ void mbar_init(uint32_t mbar, uint32_t cnt) {
    asm volatile("mbarrier.init.shared.b64 [%0], %1;" :: "r"(mbar), "r"(cnt) : "memory");
}
__device__ __forceinline__ void mbar_expect_tx(uint32_t mbar, uint32_t bytes) {
    asm volatile("mbarrier.arrive.expect_tx.shared.b64 _, [%0], %1;"
                 :: "r"(mbar), "r"(bytes) : "memory");
}
__device__ __forceinline__ void mbar_arrive(uint32_t mbar) {
    asm volatile("mbarrier.arrive.shared.b64 _, [%0];" :: "r"(mbar) : "memory");
}
__device__ __forceinline__ void mbar_wait(uint32_t mbar, uint32_t parity) {
    asm volatile(
        "{\n\t.reg .pred P;\n\t"
        "WL_%=:\n\t"
        "mbarrier.try_wait.parity.acquire.cta.shared::cta.b64 P, [%0], %1, 0x989680;\n\t"
        "@P bra.uni WD_%=;\n\t"
        "bra.uni WL_%=;\n\t"
        "WD_%=:\n\t}"
        :: "r"(mbar), "r"(parity) : "memory");
}
__device__ __forceinline__ void bulk_g2s(uint32_t dst, const void* src, uint32_t bytes, uint32_t mbar) {
    asm volatile(
        "cp.async.bulk.shared::cluster.global.mbarrier::complete_tx::bytes [%0], [%1], %2, [%3];"
        :: "r"(dst), "l"(src), "r"(bytes), "r"(mbar) : "memory");
}
__device__ __forceinline__ void fence_async() {
    asm volatile("fence.proxy.async.shared::cta;" ::: "memory");
}
__device__ __forceinline__ void mma8(float* d, const uint32_t* a, uint32_t b0, uint32_t b1) {
    asm volatile(
        "mma.sync.aligned.m16n8k8.row.col.f32.tf32.tf32.f32 "
        "{%0,%1,%2,%3}, {%4,%5,%6,%7}, {%8,%9}, {%0,%1,%2,%3};"
        : "+f"(d[0]), "+f"(d[1]), "+f"(d[2]), "+f"(d[3])
        : "r"(a[0]), "r"(a[1]), "r"(a[2]), "r"(a[3]), "r"(b0), "r"(b1));
}

// ---------------- prologue: demod ----------------
__global__ void demod_kernel(const float* __restrict__ y, const float* __restrict__ w) {
    int o = blockIdx.x, b = blockIdx.y, ci = threadIdx.x;
    float m = 1.0f + y[b * CI + ci];
    const float* wr = w + ((size_t)o * CI + ci) * 5;
    float s = wr[0]*wr[0] + wr[1]*wr[1] + wr[2]*wr[2] + wr[3]*wr[3] + wr[4]*wr[4];
    float v = m * m * s;
#pragma unroll
    for (int off = 16; off; off >>= 1) v += __shfl_xor_sync(0xffffffffu, v, off);
    __shared__ float red[8];
    if ((threadIdx.x & 31) == 0) red[threadIdx.x >> 5] = v;
    __syncthreads();
    if (threadIdx.x == 0) {
        float t = red[0]+red[1]+red[2]+red[3]+red[4]+red[5]+red[6]+red[7];
        g_demod[b * CO + o] = rsqrtf(t + EPSV);
    }
}

// ---------------- prologue: x transpose + tf32 + pad + pair interleave ----------------
__global__ __launch_bounds__(256) void prep_x_kernel(const float* __restrict__ x) {
    __shared__ float xs[16][132];
    const int t = threadIdx.x;
    const int h = blockIdx.x, ck = blockIdx.y, b = blockIdx.z;

    const float* src = x + ((size_t)(b * CI + ck * 16) * HH + h) * WW;
#pragma unroll
    for (int r = 0; r < 8; r++) {
        int idx = t + r * 256;
        int j = idx >> 7, pix = idx & 127;
        xs[j][pix] = src[(size_t)j * HH * WW + pix];
    }
    __syncthreads();

    float* dst = g_xt + ((size_t)((b * CKN + ck) * HH + h)) * XROWF;
#pragma unroll
    for (int r = 0; r < 8; r++) {
        int o = t + r * 256;
        int ks = o >> 10, pix = (o >> 3) & 127, l8 = o & 7;
        int tig = l8 >> 1, pair = l8 & 1;
        int j = ks * 8 + pair * 4 + tig;
        dst[ks * 1040 + (pix + 1) * 8 + l8] = to_tf32(xs[j][pix]);
    }
    if (t < 32) {  // zero borders: pix 0 and 129 for both ks
        int ks = t >> 4, side = (t >> 3) & 1, l8 = t & 7;
        dst[ks * 1040 + (side ? 129 : 0) * 8 + l8] = 0.0f;
    }
}

// ---------------- prologue: modulated+demodulated tf32 weights (SMEM layout) ----------
__global__ __launch_bounds__(128) void prep_w_kernel(
    const float* __restrict__ w, const float* __restrict__ y)
{
    const int ck = blockIdx.x, ct = blockIdx.y, b = blockIdx.z;
    const int co = threadIdx.x;
    const int o = ct * 128 + co;
    const float dd = g_demod[b * CO + o];
    float* blk = g_weff + ((size_t)((b * 2 + ct) * CKN + ck)) * WF;
#pragma unroll
    for (int j = 0; j < 16; j++) {
        const int ci = ck * 16 + j;
        const float m = (1.0f + y[b * CI + ci]) * dd;
        const int ks = j >> 3, rem = j & 7, pair = rem >> 2, tig = rem & 3;
        const float* wp = w + ((size_t)o * CI + ci) * 5;
#pragma unroll
        for (int tap = 0; tap < 5; tap++)
            blk[(((tap * 2 + ks) * 128 + co) << 3) + tig * 2 + pair] = to_tf32(wp[tap] * m);
    }
}

// ---------------- producer: one chunk into a stage ----------------
__device__ __forceinline__ void issue_chunk(
    int c, int h0, int b, int ct, uint32_t stage_dst, uint32_t full_mb)
{
    mbar_expect_tx(full_mb, TXBYTES);
    const float* xb = g_xt + ((size_t)(b * CKN + c) * HH) * XROWF;
    if (h0 >= 2 && h0 <= 124) {
        bulk_g2s(stage_dst, xb + (size_t)(h0 - 1) * XROWF, 4 * XROWF * 4, full_mb);
    } else if (h0 == 0) {
        bulk_g2s(stage_dst, g_zero, XROWF * 4, full_mb);
        bulk_g2s(stage_dst + XROWF * 4, xb, 3 * XROWF * 4, full_mb);
    } else { // h0 == 126
        bulk_g2s(stage_dst, xb + (size_t)125 * XROWF, 3 * XROWF * 4, full_mb);
        bulk_g2s(stage_dst + 3 * XROWF * 4, g_zero, XROWF * 4, full_mb);
    }
    bulk_g2s(stage_dst + XF * 4,
             g_weff + ((size_t)((b * 2 + ct) * CKN + c)) * WF, WF * 4, full_mb);
}

// ---------------- main: tf32 mma.sync, 512 thr, M256 x N128, 3-stage pipeline --------
__global__ __launch_bounds__(512, 1) void conv_mma_kernel(float* __restrict__ out) {
    extern __shared__ float smem[];
    const uint32_t smem_base = smem_u32(smem);
    const uint32_t barbase = smem_base + NSTAGE * STAGEF * 4;

    const int tid  = threadIdx.x;
    const int lane = tid & 31;
    const int wid  = tid >> 5;
    const int grp  = lane >> 2;
    const int tig  = lane & 3;
    const int mg = wid >> 2;             // 0..3 : M64 tile over M=256
    const int ng = wid & 3;              // 0..3 : N32 tile over N=128
    const int row = mg >> 1;             // output row within CTA (0/1)
    const int pbase = (mg & 1) * 64;     // pixel base

    const int h0 = blockIdx.x * 2;
    const int ct = blockIdx.y;
    const int b  = blockIdx.z;

    if (tid == 0) {
        for (int s = 0; s < NSTAGE; s++) {
            mbar_init(barbase + s * 8, 1);            // full
            mbar_init(barbase + 24 + s * 8, 16);      // empty (one arrive per warp)
        }
        fence_async();
    }
    __syncthreads();
    if (tid == 0)
        for (int c = 0; c < NSTAGE; c++)
            issue_chunk(c, h0, b, ct, smem_base + c * STAGEF * 4, barbase + c * 8);

    float d[4][4][4];
#pragma unroll
    for (int f = 0; f < 4; f++)
#pragma unroll
        for (int nf = 0; nf < 4; nf++)
#pragma unroll
            for (int k = 0; k < 4; k++) d[f][nf][k] = 0.0f;

    for (int c = 0; c < CKN; c++) {
        const int s = c % NSTAGE;
        const int r = c / NSTAGE;
        mbar_wait(barbase + s * 8, r & 1);
        const float* xs = smem + s * STAGEF;
        const float* ws = xs + XF;

#pragma unroll
        for (int tap = 0; tap < 5; tap++) {
            const int xrow  = row + ((tap == 0) ? 0 : (tap == 4 ? 2 : 1));
            const int shift = (tap == 1) ? -1 : ((tap == 3) ? 1 : 0);
#pragma unroll
            for (int ks = 0; ks < 2; ks++) {
                // padded, unpredicated A loads
                const float* xb0 = xs + (xrow * 2 + ks) * 1040 + tig * 2;
                uint32_t a[4][4];
#pragma unroll
                for (int f = 0; f < 4; f++) {
                    const int sp = pbase + f * 16 + grp + shift + 1;  // padded index
                    const uint2 lo = *(const uint2*)(xb0 + sp * 8);
                    const uint2 hi = *(const uint2*)(xb0 + (sp + 8) * 8);
                    a[f][0] = lo.x; a[f][2] = lo.y;
                    a[f][1] = hi.x; a[f][3] = hi.y;
                }
                const float* wb = ws + (((tap * 2 + ks) * 128 + ng * 32 + grp) << 3) + tig * 2;
#pragma unroll
                for (int nf = 0; nf < 4; nf++) {
                    const uint2 bv = *(const uint2*)(wb + nf * 64);
                    mma8(d[0][nf], a[0], bv.x, bv.y);
                    mma8(d[1][nf], a[1], bv.x, bv.y);
                    mma8(d[2][nf], a[2], bv.x, bv.y);
                    mma8(d[3][nf], a[3], bv.x, bv.y);
                }
            }
        }
        if (lane == 0) mbar_arrive(barbase + 24 + s * 8);
        if (tid == 0 && c + NSTAGE < CKN) {
            mbar_wait(barbase + 24 + s * 8, r & 1);
            issue_chunk(c + NSTAGE, h0, b, ct, smem_base + s * STAGEF * 4, barbase + s * 8);
        }
    }

    // ---- epilogue: demod folded into weights -> pure store ----
    float* ob = out + (((size_t)b * CO + ct * 128) * HH + (h0 + row)) * WW;
#pragma unroll
    for (int f = 0; f < 4; f++) {
        const int p = pbase + f * 16 + grp;
#pragma unroll
        for (int nf = 0; nf < 4; nf++) {
            const int co = ng * 32 + nf * 8 + tig * 2;
            ob[(size_t)co * (HH * WW) + p]           = d[f][nf][0];
            ob[(size_t)(co + 1) * (HH * WW) + p]     = d[f][nf][1];
            ob[(size_t)co * (HH * WW) + p + 8]       = d[f][nf][2];
            ob[(size_t)(co + 1) * (HH * WW) + p + 8] = d[f][nf][3];
        }
    }
}

extern "C" void kernel_launch(void* const* d_in, const int* in_sizes, int n_in,
                              void* d_out, int out_size) {
    const float* x = (const float*)d_in[0];
    const float* y = (const float*)d_in[1];
    const float* w = (const float*)d_in[2];
    float* out = (float*)d_out;

    cudaFuncSetAttribute(conv_mma_kernel, cudaFuncAttributeMaxDynamicSharedMemorySize, SMEM_DYN);

    demod_kernel<<<dim3(CO, BS), 256>>>(y, w);
    prep_x_kernel<<<dim3(HH, CKN, BS), 256>>>(x);
    prep_w_kernel<<<dim3(CKN, 2, BS), 128>>>(w, y);
    conv_mma_kernel<<<dim3(HH / 2, 2, BS), 512, SMEM_DYN>>>(out);
}

// round 7
// speedup vs baseline: 7.1992x; 1.7421x over previous
#include <cuda_runtime.h>
#include <cuda_fp16.h>
#include <cstdint>
#include <cstddef>

#define BS 8
#define CI 256
#define CO 256
#define HH 128
#define WW 128
#define EPSV 1e-6f

#define CKN 16                    // ci chunks of 16
// Stage layout (halves):
//  X: [xrow 4][pix 130 padded][16 slots] = 8320 halves (16640 B)
//  W: [tap 5][co 128][16 slots]          = 10240 halves (20480 B)
#define XROWH 2080
#define XH (4 * XROWH)            // 8320
#define WH 10240
#define STAGEH (XH + WH)          // 18560 halves = 37120 B
#define NSTAGE 4
#define TXBYTES (STAGEH * 2)
#define SMEM_DYN (NSTAGE * STAGEH * 2 + 256)

// ---------------- device scratch (no cudaMalloc allowed) ----------------
// x: fp16, padded, slot-interleaved: block (b*16+ck)*128+h of 2080 halves:
//    [pix 0..129][slot 16]; slot pairs p: p=2t -> ci(2t,2t+1), p=2t+1 -> ci(2t+8,2t+9)
__device__ __align__(16) __half g_xt[(size_t)BS * CKN * HH * XROWH];
// w_eff = fp16(w * (1+y) * demod): block ((b*2+ct)*16+ck): [tap][co][slot 16]
__device__ __align__(16) __half g_weff[(size_t)BS * 2 * CKN * WH];
__device__ float g_demod[BS * CO];
__device__ __align__(16) __half g_zero[XROWH];   // zero halo row (.bss)

// ---------------- PTX helpers (base sm_103 legal; NO tcgen05) ----------------
__device__ __forceinline__ uint32_t smem_u32(const void* p) {
    uint32_t a;
    asm("{ .reg .u64 t; cvta.to.shared.u64 t, %1; cvt.u32.u64 %0, t; }" : "=r"(a) : "l"(p));
    return a;
}
__device__ __forceinline__ void mbar_init(uint32_t mbar, uint32_t cnt) {
    asm volatile("mbarrier.init.shared.b64 [%0], %1;" :: "r"(mbar), "r"(cnt) : "memory");
}
__device__ __forceinline__ void mbar_expect_tx(uint32_t mbar, uint32_t bytes) {
    asm volatile("mbarrier.arrive.expect_tx.shared.b64 _, [%0], %1;"
                 :: "r"(mbar), "r"(bytes) : "memory");
}
__device__ __forceinline__ void mbar_arrive(uint32_t mbar) {
    asm volatile("mbarrier.arrive.shared.b64 _, [%0];" :: "r"(mbar) : "memory");
}
__device__ __forceinline__ void mbar_wait(uint32_t mbar, uint32_t parity) {
    asm volatile(
        "{\n\t.reg .pred P;\n\t"
        "WL_%=:\n\t"
        "mbarrier.try_wait.parity.acquire.cta.shared::cta.b64 P, [%0], %1, 0x989680;\n\t"
        "@P bra.uni WD_%=;\n\t"
        "bra.uni WL_%=;\n\t"
        "WD_%=:\n\t}"
        :: "r"(mbar), "r"(parity) : "memory");
}
__device__ __forceinline__ void bulk_g2s(uint32_t dst, const void* src, uint32_t bytes, uint32_t mbar) {
    asm volatile(
        "cp.async.bulk.shared::cluster.global.mbarrier::complete_tx::bytes [%0], [%1], %2, [%3];"
        :: "r"(dst), "l"(src), "r"(bytes), "r"(mbar) : "memory");
}
__device__ __forceinline__ void fence_async() {
    asm volatile("fence.proxy.async.shared::cta;" ::: "memory");
}
// m16n8k16 fp16 MMA, fp32 accumulate
__device__ __forceinline__ void mma16(float* d, const uint32_t* a, uint32_t b0, uint32_t b1) {
    asm volatile(
        "mma.sync.aligned.m16n8k16.row.col.f32.f16.f16.f32 "
        "{%0,%1,%2,%3}, {%4,%5,%6,%7}, {%8,%9}, {%0,%1,%2,%3};"
        : "+f"(d[0]), "+f"(d[1]), "+f"(d[2]), "+f"(d[3])
        : "r"(a[0]), "r"(a[1]), "r"(a[2]), "r"(a[3]), "r"(b0), "r"(b1));
}

// ---------------- prologue: demod ----------------
__global__ void demod_kernel(const float* __restrict__ y, const float* __restrict__ w) {
    int o = blockIdx.x, b = blockIdx.y, ci = threadIdx.x;
    float m = 1.0f + y[b * CI + ci];
    const float* wr = w + ((size_t)o * CI + ci) * 5;
    float s = wr[0]*wr[0] + wr[1]*wr[1] + wr[2]*wr[2] + wr[3]*wr[3] + wr[4]*wr[4];
    float v = m * m * s;
#pragma unroll
    for (int off = 16; off; off >>= 1) v += __shfl_xor_sync(0xffffffffu, v, off);
    __shared__ float red[8];
    if ((threadIdx.x & 31) == 0) red[threadIdx.x >> 5] = v;
    __syncthreads();
    if (threadIdx.x == 0) {
        float t = red[0]+red[1]+red[2]+red[3]+red[4]+red[5]+red[6]+red[7];
        g_demod[b * CO + o] = rsqrtf(t + EPSV);
    }
}

// ---------------- prologue: x -> fp16, transpose, pad, slot-interleave ----------------
__global__ __launch_bounds__(256) void prep_x_kernel(const float* __restrict__ x) {
    __shared__ float xs[16][132];
    const int t = threadIdx.x;
    const int h = blockIdx.x, ck = blockIdx.y, b = blockIdx.z;

    const float* src = x + ((size_t)(b * CI + ck * 16) * HH + h) * WW;
#pragma unroll
    for (int r = 0; r < 8; r++) {
        int idx = t + r * 256;
        int j = idx >> 7, pix = idx & 127;
        xs[j][pix] = src[(size_t)j * HH * WW + pix];
    }
    __syncthreads();

    __half2* dst = (__half2*)(g_xt + ((size_t)((b * CKN + ck) * HH + h)) * XROWH);
#pragma unroll
    for (int r = 0; r < 4; r++) {
        int o = t + r * 256;               // 0..1023: pix*8 + pairslot
        int pix = o >> 3, p = o & 7;
        int ci0 = ((p >> 1) << 1) + ((p & 1) << 3);   // p=2t -> 2t ; p=2t+1 -> 2t+8
        dst[(pix + 1) * 8 + p] = __floats2half2_rn(xs[ci0][pix], xs[ci0 + 1][pix]);
    }
    if (t < 16) {   // zero borders: pix 0 and 129
        int side = t >> 3, p = t & 7;
        dst[(side ? 129 : 0) * 8 + p] = __floats2half2_rn(0.f, 0.f);
    }
}

// ---------------- prologue: modulated+demodulated fp16 weights (SMEM layout) ----------
__global__ __launch_bounds__(128) void prep_w_kernel(
    const float* __restrict__ w, const float* __restrict__ y)
{
    const int ck = blockIdx.x, ct = blockIdx.y, b = blockIdx.z;
    const int co = threadIdx.x;
    const int o = ct * 128 + co;
    const float dd = g_demod[b * CO + o];
    __half2* blk = (__half2*)(g_weff + ((size_t)((b * 2 + ct) * CKN + ck)) * WH);
#pragma unroll
    for (int p = 0; p < 8; p++) {
        const int j0 = ((p >> 1) << 1) + ((p & 1) << 3);
        const int ci0 = ck * 16 + j0;
        const float m0 = (1.0f + y[b * CI + ci0]) * dd;
        const float m1 = (1.0f + y[b * CI + ci0 + 1]) * dd;
        const float* wp0 = w + ((size_t)o * CI + ci0) * 5;
        const float* wp1 = wp0 + 5;
#pragma unroll
        for (int tap = 0; tap < 5; tap++)
            blk[(tap * 128 + co) * 8 + p] = __floats2half2_rn(wp0[tap] * m0, wp1[tap] * m1);
    }
}

// ---------------- producer: one chunk into a stage ----------------
__device__ __forceinline__ void issue_chunk(
    int c, int h0, int b, int ct, uint32_t stage_dst, uint32_t full_mb)
{
    mbar_expect_tx(full_mb, TXBYTES);
    const __half* xb = g_xt + ((size_t)(b * CKN + c) * HH) * XROWH;
    if (h0 >= 2 && h0 <= 124) {
        bulk_g2s(stage_dst, xb + (size_t)(h0 - 1) * XROWH, 4 * XROWH * 2, full_mb);
    } else if (h0 == 0) {
        bulk_g2s(stage_dst, g_zero, XROWH * 2, full_mb);
        bulk_g2s(stage_dst + XROWH * 2, xb, 3 * XROWH * 2, full_mb);
    } else { // h0 == 126
        bulk_g2s(stage_dst, xb + (size_t)125 * XROWH, 3 * XROWH * 2, full_mb);
        bulk_g2s(stage_dst + 3 * XROWH * 2, g_zero, XROWH * 2, full_mb);
    }
    bulk_g2s(stage_dst + XH * 2,
             g_weff + ((size_t)((b * 2 + ct) * CKN + c)) * WH, WH * 2, full_mb);
}

// ---------------- main: fp16 mma.sync m16n8k16, 512 thr, M256 x N128, 4 stages -------
__global__ __launch_bounds__(512, 1) void conv_mma_kernel(float* __restrict__ out) {
    extern __shared__ __half smem[];
    const uint32_t smem_base = smem_u32(smem);
    const uint32_t barbase = smem_base + NSTAGE * STAGEH * 2;

    const int tid  = threadIdx.x;
    const int lane = tid & 31;
    const int wid  = tid >> 5;
    const int grp  = lane >> 2;
    const int tig  = lane & 3;
    const int mg = wid >> 2;             // 0..3 : M64 tile over M=256
    const int ng = wid & 3;              // 0..3 : N32 tile over N=128
    const int row = mg >> 1;             // output row within CTA (0/1)
    const int pbase = (mg & 1) * 64;     // pixel base

    const int h0 = blockIdx.x * 2;
    const int ct = blockIdx.y;
    const int b  = blockIdx.z;

    if (tid == 0) {
        for (int s = 0; s < NSTAGE; s++) {
            mbar_init(barbase + s * 8, 1);                    // full
            mbar_init(barbase + NSTAGE * 8 + s * 8, 16);      // empty (per warp)
        }
        fence_async();
    }
    __syncthreads();
    if (tid == 0)
        for (int c = 0; c < NSTAGE; c++)
            issue_chunk(c, h0, b, ct, smem_base + c * STAGEH * 2, barbase + c * 8);

    float d[4][4][4];
#pragma unroll
    for (int f = 0; f < 4; f++)
#pragma unroll
        for (int nf = 0; nf < 4; nf++)
#pragma unroll
            for (int k = 0; k < 4; k++) d[f][nf][k] = 0.0f;

    for (int c = 0; c < CKN; c++) {
        const int s = c % NSTAGE;
        const int r = c / NSTAGE;
        mbar_wait(barbase + s * 8, r & 1);
        const __half* xs = smem + s * STAGEH;
        const __half* ws = xs + XH;

#pragma unroll
        for (int tap = 0; tap < 5; tap++) {
            const int xrow  = row + ((tap == 0) ? 0 : (tap == 4 ? 2 : 1));
            const int shift = (tap == 1) ? -1 : ((tap == 3) ? 1 : 0);

            const __half* xb0 = xs + xrow * XROWH + tig * 4;
            uint32_t a[4][4];
#pragma unroll
            for (int f = 0; f < 4; f++) {
                const int sp = pbase + f * 16 + grp + shift + 1;  // padded index
                const uint2 lo = *(const uint2*)(xb0 + sp * 16);          // row grp
                const uint2 hi = *(const uint2*)(xb0 + (sp + 8) * 16);    // row grp+8
                a[f][0] = lo.x;   // (pix, k 2t..2t+1)
                a[f][1] = hi.x;   // (pix+8, k 2t..2t+1)
                a[f][2] = lo.y;   // (pix, k 2t+8..2t+9)
                a[f][3] = hi.y;   // (pix+8, k 2t+8..2t+9)
            }
            const __half* wb = ws + (tap * 128 + ng * 32 + grp) * 16 + tig * 4;
#pragma unroll
            for (int nf = 0; nf < 4; nf++) {
                const uint2 bv = *(const uint2*)(wb + nf * 128);
                mma16(d[0][nf], a[0], bv.x, bv.y);
                mma16(d[1][nf], a[1], bv.x, bv.y);
                mma16(d[2][nf], a[2], bv.x, bv.y);
                mma16(d[3][nf], a[3], bv.x, bv.y);
            }
        }
        if (lane == 0) mbar_arrive(barbase + NSTAGE * 8 + s * 8);
        if (tid == 0 && c + NSTAGE < CKN) {
            mbar_wait(barbase + NSTAGE * 8 + s * 8, r & 1);
            issue_chunk(c + NSTAGE, h0, b, ct, smem_base + s * STAGEH * 2, barbase + s * 8);
        }
    }

    // ---- epilogue: demod folded into weights -> pure store ----
    float* ob = out + (((size_t)b * CO + ct * 128) * HH + (h0 + row)) * WW;
#pragma unroll
    for (int f = 0; f < 4; f++) {
        const int p = pbase + f * 16 + grp;
#pragma unroll
        for (int nf = 0; nf < 4; nf++) {
            const int co = ng * 32 + nf * 8 + tig * 2;
            ob[(size_t)co * (HH * WW) + p]           = d[f][nf][0];
            ob[(size_t)(co + 1) * (HH * WW) + p]     = d[f][nf][1];
            ob[(size_t)co * (HH * WW) + p + 8]       = d[f][nf][2];
            ob[(size_t)(co + 1) * (HH * WW) + p + 8] = d[f][nf][3];
        }
    }
}

extern "C" void kernel_launch(void* const* d_in, const int* in_sizes, int n_in,
                              void* d_out, int out_size) {
    const float* x = (const float*)d_in[0];
    const float* y = (const float*)d_in[1];
    const float* w = (const float*)d_in[2];
    float* out = (float*)d_out;

    cudaFuncSetAttribute(conv_mma_kernel, cudaFuncAttributeMaxDynamicSharedMemorySize, SMEM_DYN);

    demod_kernel<<<dim3(CO, BS), 256>>>(y, w);
    prep_x_kernel<<<dim3(HH, CKN, BS), 256>>>(x);
    prep_w_kernel<<<dim3(CKN, 2, BS), 128>>>(w, y);
    conv_mma_kernel<<<dim3(HH / 2, 2, BS), 512, SMEM_DYN>>>(out);
}